// round 9
// baseline (speedup 1.0000x reference)
#include <cuda_runtime.h>
#include <cuda_bf16.h>
#include <math.h>
#include <stdint.h>

#define SEQ   2048
#define HID   1024
#define NHEAD 16
#define DK    64

// __device__ scratch (allocation-free rule)
__device__ __nv_bfloat16 g_Xh[3 * SEQ * HID];
__device__ __nv_bfloat16 g_Xl[3 * SEQ * HID];
__device__ __nv_bfloat16 g_Wh[4 * HID * HID];
__device__ __nv_bfloat16 g_Wl[4 * HID * HID];
__device__ __nv_bfloat16 g_Qhh[NHEAD * SEQ * DK];
__device__ __nv_bfloat16 g_Qll[NHEAD * SEQ * DK];
__device__ __nv_bfloat16 g_Khh[NHEAD * SEQ * DK];
__device__ __nv_bfloat16 g_Kll[NHEAD * SEQ * DK];
__device__ __nv_bfloat16 g_Vhh[NHEAD * SEQ * DK];
__device__ __nv_bfloat16 g_Vll[NHEAD * SEQ * DK];
__device__ __nv_bfloat16 g_Obh[SEQ * HID];
__device__ __nv_bfloat16 g_Obl[SEQ * HID];
__device__ uint32_t g_mbits[SEQ * (SEQ / 32)];

// ---------------------------------------------------------------------------
// helpers
// ---------------------------------------------------------------------------
__device__ __forceinline__ uint32_t smem_u32(const void* p) {
    uint32_t r;
    asm("{ .reg .u64 t; cvta.to.shared.u64 t, %1; cvt.u32.u64 %0, t; }"
        : "=r"(r) : "l"(p));
    return r;
}
__device__ __forceinline__ void ldsm_x4(uint32_t r[4], uint32_t addr) {
    asm volatile("ldmatrix.sync.aligned.m8n8.x4.shared.b16 {%0,%1,%2,%3}, [%4];"
                 : "=r"(r[0]), "=r"(r[1]), "=r"(r[2]), "=r"(r[3]) : "r"(addr));
}
__device__ __forceinline__ void ldsm_x4t(uint32_t r[4], uint32_t addr) {
    asm volatile("ldmatrix.sync.aligned.m8n8.x4.trans.shared.b16 {%0,%1,%2,%3}, [%4];"
                 : "=r"(r[0]), "=r"(r[1]), "=r"(r[2]), "=r"(r[3]) : "r"(addr));
}
__device__ __forceinline__ void mma_bf16(float d[4], const uint32_t a[4],
                                         uint32_t b0, uint32_t b1) {
    asm volatile(
        "mma.sync.aligned.m16n8k16.row.col.f32.bf16.bf16.f32 "
        "{%0,%1,%2,%3}, {%4,%5,%6,%7}, {%8,%9}, {%0,%1,%2,%3};"
        : "+f"(d[0]), "+f"(d[1]), "+f"(d[2]), "+f"(d[3])
        : "r"(a[0]), "r"(a[1]), "r"(a[2]), "r"(a[3]), "r"(b0), "r"(b1));
}
__device__ __forceinline__ uint32_t pk(float x, float y) {
    uint32_t r;
    asm("cvt.rn.bf16x2.f32 %0, %1, %2;" : "=r"(r) : "f"(y), "f"(x));
    return r;
}
__device__ __forceinline__ float bf_hi_f(float x) {
    return __bfloat162float(__float2bfloat16(x));
}
__device__ __forceinline__ void cp16(uint32_t saddr, const void* gaddr) {
    asm volatile("cp.async.cg.shared.global [%0], [%1], 16;"
                 :: "r"(saddr), "l"(gaddr) : "memory");
}
#define CP_COMMIT() asm volatile("cp.async.commit_group;" ::: "memory")
#define CP_WAIT1()  asm volatile("cp.async.wait_group 1;" ::: "memory")

// ---------------------------------------------------------------------------
// hi/lo split conversions
// ---------------------------------------------------------------------------
__global__ __launch_bounds__(256) void cvt_inputs(const float* __restrict__ q,
                                                  const float* __restrict__ k,
                                                  const float* __restrict__ v) {
    const int z = blockIdx.y;
    const float* src = (z == 0) ? q : (z == 1) ? k : v;
    __nv_bfloat16* dh = g_Xh + (size_t)z * SEQ * HID;
    __nv_bfloat16* dl = g_Xl + (size_t)z * SEQ * HID;
    const int idx = blockIdx.x * 256 + threadIdx.x;
    float4 x = ((const float4*)src)[idx];
    uint2 h, l;
    h.x = pk(bf_hi_f(x.x), bf_hi_f(x.y));
    h.y = pk(bf_hi_f(x.z), bf_hi_f(x.w));
    l.x = pk(x.x - bf_hi_f(x.x), x.y - bf_hi_f(x.y));
    l.y = pk(x.z - bf_hi_f(x.z), x.w - bf_hi_f(x.w));
    ((uint2*)dh)[idx] = h;
    ((uint2*)dl)[idx] = l;
}

__global__ __launch_bounds__(256) void cvt_weights(const float* __restrict__ wq,
                                                   const float* __restrict__ wk,
                                                   const float* __restrict__ wv,
                                                   const float* __restrict__ wo) {
    const int z = blockIdx.y;
    const float* src = (z == 0) ? wq : (z == 1) ? wk : (z == 2) ? wv : wo;
    __nv_bfloat16* dh = g_Wh + (size_t)z * HID * HID;
    __nv_bfloat16* dl = g_Wl + (size_t)z * HID * HID;
    const int idx = blockIdx.x * 256 + threadIdx.x;
    float4 x = ((const float4*)src)[idx];
    uint2 h, l;
    h.x = pk(bf_hi_f(x.x), bf_hi_f(x.y));
    h.y = pk(bf_hi_f(x.z), bf_hi_f(x.w));
    l.x = pk(x.x - bf_hi_f(x.x), x.y - bf_hi_f(x.y));
    l.y = pk(x.z - bf_hi_f(x.z), x.w - bf_hi_f(x.w));
    ((uint2*)dh)[idx] = h;
    ((uint2*)dl)[idx] = l;
}

// ---------------------------------------------------------------------------
// mask bit-pack
// ---------------------------------------------------------------------------
__global__ __launch_bounds__(256) void pack_mask(const int* __restrict__ mask) {
    int widx = blockIdx.x * 256 + threadIdx.x;
    int q = widx >> 6;
    int w = widx & 63;
    const int4* p = (const int4*)(mask + (size_t)q * SEQ + w * 32);
    uint32_t bits = 0;
#pragma unroll
    for (int i = 0; i < 8; i++) {
        int4 m = p[i];
        bits |= (m.x != 0 ? 1u : 0u) << (4 * i + 0);
        bits |= (m.y != 0 ? 1u : 0u) << (4 * i + 1);
        bits |= (m.z != 0 ? 1u : 0u) << (4 * i + 2);
        bits |= (m.w != 0 ? 1u : 0u) << (4 * i + 3);
    }
    g_mbits[widx] = bits;
}

// ---------------------------------------------------------------------------
// bf16-split GEMM, BK=64, 3-stage cp.async pipeline.
// 3 virtual passes [AhBh],[AlBh],[AhBl] over K=1024 -> NT = 48 tiles.
// CTA 128x128, 8 warps (2m x 4n), warp tile 64x32.
// ---------------------------------------------------------------------------
#define SROW 72                        // bf16 per row (64 + 8 pad) -> 144 B
#define TILE_BYTES (128 * SROW * 2)    // 18432
#define STAGE_BYTES (2 * TILE_BYTES)   // A + B = 36864
#define NSTAGE 3
#define GEMM_SMEM (NSTAGE * STAGE_BYTES)   // 110592

template <int MODE>
__device__ __forceinline__ void gemm_body(const __nv_bfloat16* __restrict__ Ah,
                                          const __nv_bfloat16* __restrict__ Al,
                                          const __nv_bfloat16* __restrict__ Bh,
                                          const __nv_bfloat16* __restrict__ Bl,
                                          const float* __restrict__ bias,
                                          float* __restrict__ Cf,
                                          __nv_bfloat16* __restrict__ Chi,
                                          __nv_bfloat16* __restrict__ Clo) {
    extern __shared__ char dynsm[];
    const uint32_t sb = smem_u32(dynsm);

    const int tid  = threadIdx.x;
    const int lane = tid & 31;
    const int w    = tid >> 5;
    const int wm   = w >> 2;
    const int wn   = w & 3;
    const int m0   = blockIdx.x * 128;
    const int n0   = blockIdx.y * 128;

    const int lrow = tid >> 1;          // 0..127
    const int lcb  = (tid & 1) * 4;     // chunk base (16B chunks, 8/row)

    float acc[4][4][4];
#pragma unroll
    for (int i = 0; i < 4; i++)
#pragma unroll
        for (int j = 0; j < 4; j++)
#pragma unroll
            for (int e = 0; e < 4; e++) acc[i][j][e] = 0.f;

    auto issue = [&](int t) {
        const int pass = t >> 4;
        const int k0   = (t & 15) * 64;
        const __nv_bfloat16* As = (pass == 1) ? Al : Ah;
        const __nv_bfloat16* Bs = (pass == 2) ? Bl : Bh;
        const uint32_t st = sb + (uint32_t)(t % NSTAGE) * STAGE_BYTES;
#pragma unroll
        for (int qq = 0; qq < 4; qq++) {
            const uint32_t so = (uint32_t)(lrow * 144 + (lcb + qq) * 16);
            cp16(st + so, As + (size_t)(m0 + lrow) * HID + k0 + (lcb + qq) * 8);
            cp16(st + TILE_BYTES + so, Bs + (size_t)(n0 + lrow) * HID + k0 + (lcb + qq) * 8);
        }
        CP_COMMIT();
    };

    issue(0); issue(1);

    const int NT = 48;
    for (int t = 0; t < NT; t++) {
        CP_WAIT1();
        __syncthreads();
        if (t + 2 < NT) issue(t + 2);

        const uint32_t sAb = sb + (uint32_t)(t % NSTAGE) * STAGE_BYTES;
        const uint32_t sBb = sAb + TILE_BYTES;
#pragma unroll
        for (int kk = 0; kk < 4; kk++) {
            uint32_t afr[4][4], bfr[2][4];
#pragma unroll
            for (int i = 0; i < 4; i++)
                ldsm_x4(afr[i], sAb + 2u * ((wm * 64 + 16 * i + (lane & 15)) * SROW
                                            + kk * 16 + ((lane >> 4) & 1) * 8));
#pragma unroll
            for (int j2 = 0; j2 < 2; j2++)
                ldsm_x4(bfr[j2], sBb + 2u * ((wn * 32 + 16 * j2 + (lane & 7)
                                              + ((lane >> 4) & 1) * 8) * SROW
                                             + kk * 16 + ((lane >> 3) & 1) * 8));
#pragma unroll
            for (int i = 0; i < 4; i++)
#pragma unroll
                for (int j2 = 0; j2 < 2; j2++) {
                    mma_bf16(acc[i][2 * j2],     afr[i], bfr[j2][0], bfr[j2][1]);
                    mma_bf16(acc[i][2 * j2 + 1], afr[i], bfr[j2][2], bfr[j2][3]);
                }
        }
    }

    // epilogue
#pragma unroll
    for (int j = 0; j < 4; j++) {
        const int gn0 = n0 + wn * 32 + 8 * j + 2 * (lane & 3);
        const float b0 = __ldg(bias + gn0);
        const float b1 = __ldg(bias + gn0 + 1);
#pragma unroll
        for (int i = 0; i < 4; i++) {
            const int r0 = m0 + wm * 64 + 16 * i + (lane >> 2);
            const int r1 = r0 + 8;
            float c0 = acc[i][j][0] + b0, c1 = acc[i][j][1] + b1;
            float c2 = acc[i][j][2] + b0, c3 = acc[i][j][3] + b1;
            if (MODE == 1) {
                *(float2*)(Cf + (size_t)r0 * HID + gn0) = make_float2(c0, c1);
                *(float2*)(Cf + (size_t)r1 * HID + gn0) = make_float2(c2, c3);
            } else {
                const int head = gn0 >> 6;
                const int d    = gn0 & 63;
                size_t i0 = ((size_t)head * SEQ + r0) * DK + d;
                size_t i1 = ((size_t)head * SEQ + r1) * DK + d;
                *(uint32_t*)(Chi + i0) = pk(bf_hi_f(c0), bf_hi_f(c1));
                *(uint32_t*)(Clo + i0) = pk(c0 - bf_hi_f(c0), c1 - bf_hi_f(c1));
                *(uint32_t*)(Chi + i1) = pk(bf_hi_f(c2), bf_hi_f(c3));
                *(uint32_t*)(Clo + i1) = pk(c2 - bf_hi_f(c2), c3 - bf_hi_f(c3));
            }
        }
    }
}

__global__ __launch_bounds__(256, 2) void qkv_gemm(
    const float* __restrict__ bq, const float* __restrict__ bk,
    const float* __restrict__ bv) {
    const int z = blockIdx.z;
    const __nv_bfloat16* Ah = g_Xh + (size_t)z * SEQ * HID;
    const __nv_bfloat16* Al = g_Xl + (size_t)z * SEQ * HID;
    const __nv_bfloat16* Bh = g_Wh + (size_t)z * HID * HID;
    const __nv_bfloat16* Bl = g_Wl + (size_t)z * HID * HID;
    const float* bias = (z == 0) ? bq : (z == 1) ? bk : bv;
    __nv_bfloat16 *Ch, *Cl;
    if (z == 0)      { Ch = g_Qhh; Cl = g_Qll; }
    else if (z == 1) { Ch = g_Khh; Cl = g_Kll; }
    else             { Ch = g_Vhh; Cl = g_Vll; }
    gemm_body<0>(Ah, Al, Bh, Bl, bias, nullptr, Ch, Cl);
}

__global__ __launch_bounds__(256, 2) void out_gemm(
    const float* __restrict__ bo, float* __restrict__ out) {
    gemm_body<1>(g_Obh, g_Obl, g_Wh + (size_t)3 * HID * HID,
                 g_Wl + (size_t)3 * HID * HID, bo, out, nullptr, nullptr);
}

// ---------------------------------------------------------------------------
// Attention: per (128 q-rows, head) CTA. 8 warps x 16 q-rows. Keyblock 128.
// Q fragments in registers (loaded once). K/V via 3-stage cp.async pipeline.
// ---------------------------------------------------------------------------
#define AROW 72
#define ATILE_B (128 * AROW * 2)          // 18432 bytes per tile
#define ASTAGE_B (4 * ATILE_B)            // Kh,Kl,Vh,Vl = 73728
#define ANSTAGE 3
#define ASMEM_BYTES (ANSTAGE * ASTAGE_B)  // 221184

__global__ __launch_bounds__(256) void attn_kernel() {
    extern __shared__ char asm_[];
    const uint32_t sb = smem_u32(asm_);

    const int tid  = threadIdx.x;
    const int lane = tid & 31;
    const int w    = tid >> 5;
    const int head = blockIdx.y;
    const int q0   = blockIdx.x * 128;

    const size_t hbase = (size_t)head * SEQ * DK;
    const int row0g = q0 + 16 * w + (lane >> 2);
    const int row1g = row0g + 8;
    const int cfr   = 2 * (lane & 3);

    // Q fragments in registers (A-layout m16k16 per kk)
    uint32_t qfh[4][4], qfl[4][4];
#pragma unroll
    for (int kk = 0; kk < 4; kk++) {
        const size_t c = kk * 16 + cfr;
        qfh[kk][0] = *(const uint32_t*)(g_Qhh + hbase + (size_t)row0g * DK + c);
        qfh[kk][1] = *(const uint32_t*)(g_Qhh + hbase + (size_t)row1g * DK + c);
        qfh[kk][2] = *(const uint32_t*)(g_Qhh + hbase + (size_t)row0g * DK + c + 8);
        qfh[kk][3] = *(const uint32_t*)(g_Qhh + hbase + (size_t)row1g * DK + c + 8);
        qfl[kk][0] = *(const uint32_t*)(g_Qll + hbase + (size_t)row0g * DK + c);
        qfl[kk][1] = *(const uint32_t*)(g_Qll + hbase + (size_t)row1g * DK + c);
        qfl[kk][2] = *(const uint32_t*)(g_Qll + hbase + (size_t)row0g * DK + c + 8);
        qfl[kk][3] = *(const uint32_t*)(g_Qll + hbase + (size_t)row1g * DK + c + 8);
    }

    const int lrow = tid >> 1;
    const int lcb  = (tid & 1) * 4;

    auto issue_kv = [&](int kb) {
        const uint32_t st = sb + (uint32_t)(kb % ANSTAGE) * ASTAGE_B;
        const size_t gr = hbase + (size_t)(kb * 128 + lrow) * DK;
#pragma unroll
        for (int qq = 0; qq < 4; qq++) {
            const uint32_t so = (uint32_t)(lrow * 144 + (lcb + qq) * 16);
            const size_t  go = gr + (lcb + qq) * 8;
            cp16(st + so,                go + g_Khh);
            cp16(st + ATILE_B + so,      go + g_Kll);
            cp16(st + 2 * ATILE_B + so,  go + g_Vhh);
            cp16(st + 3 * ATILE_B + so,  go + g_Vll);
        }
        CP_COMMIT();
    };

    issue_kv(0); issue_kv(1);

    float oacc[8][4];
#pragma unroll
    for (int j = 0; j < 8; j++)
#pragma unroll
        for (int e = 0; e < 4; e++) oacc[j][e] = 0.f;
    float mrow[2] = {-1e30f, -1e30f};
    float lrow_[2] = {0.f, 0.f};

    for (int kb = 0; kb < SEQ / 128; kb++) {
        CP_WAIT1();
        __syncthreads();
        if (kb + 2 < SEQ / 128) issue_kv(kb + 2);

        const uint32_t bKh = sb + (uint32_t)(kb % ANSTAGE) * ASTAGE_B;
        const uint32_t bKl = bKh + ATILE_B;
        const uint32_t bVh = bKh + 2 * ATILE_B;
        const uint32_t bVl = bKh + 3 * ATILE_B;

        // ---- S = Q K^T (3-pass split) ----
        float sacc[16][4];
#pragma unroll
        for (int j = 0; j < 16; j++)
#pragma unroll
            for (int e = 0; e < 4; e++) sacc[j][e] = 0.f;

        const uint32_t kroff = 2u * (((lane & 7) + ((lane >> 4) & 1) * 8) * AROW
                                     + ((lane >> 3) & 1) * 8);
#pragma unroll
        for (int kk = 0; kk < 4; kk++) {
#pragma unroll
            for (int j2 = 0; j2 < 8; j2++) {
                uint32_t kf[4];
                ldsm_x4(kf, bKh + kroff + 2u * (16 * j2 * AROW + kk * 16));
                mma_bf16(sacc[2 * j2],     qfh[kk], kf[0], kf[1]);
                mma_bf16(sacc[2 * j2],     qfl[kk], kf[0], kf[1]);
                mma_bf16(sacc[2 * j2 + 1], qfh[kk], kf[2], kf[3]);
                mma_bf16(sacc[2 * j2 + 1], qfl[kk], kf[2], kf[3]);
            }
#pragma unroll
            for (int j2 = 0; j2 < 8; j2++) {
                uint32_t kf[4];
                ldsm_x4(kf, bKl + kroff + 2u * (16 * j2 * AROW + kk * 16));
                mma_bf16(sacc[2 * j2],     qfh[kk], kf[0], kf[1]);
                mma_bf16(sacc[2 * j2 + 1], qfh[kk], kf[2], kf[3]);
            }
        }

        // ---- mask (quirk: masked -> literal 0.0) + scale ----
        uint32_t mw0[4], mw1[4];
#pragma unroll
        for (int i = 0; i < 4; i++) {
            mw0[i] = g_mbits[(size_t)row0g * 64 + kb * 4 + i];
            mw1[i] = g_mbits[(size_t)row1g * 64 + kb * 4 + i];
        }
#pragma unroll
        for (int j = 0; j < 16; j++) {
            int kl = 8 * j + 2 * (lane & 3);
            uint32_t w0 = mw0[kl >> 5], w1 = mw1[kl >> 5];
            int b = kl & 31;
            sacc[j][0] = ((w0 >> b) & 1)       ? sacc[j][0] * 0.125f : 0.f;
            sacc[j][1] = ((w0 >> (b + 1)) & 1) ? sacc[j][1] * 0.125f : 0.f;
            sacc[j][2] = ((w1 >> b) & 1)       ? sacc[j][2] * 0.125f : 0.f;
            sacc[j][3] = ((w1 >> (b + 1)) & 1) ? sacc[j][3] * 0.125f : 0.f;
        }

        // ---- online softmax ----
        float mx0 = -1e30f, mx1 = -1e30f;
#pragma unroll
        for (int j = 0; j < 16; j++) {
            mx0 = fmaxf(mx0, fmaxf(sacc[j][0], sacc[j][1]));
            mx1 = fmaxf(mx1, fmaxf(sacc[j][2], sacc[j][3]));
        }
        mx0 = fmaxf(mx0, __shfl_xor_sync(0xffffffffu, mx0, 1, 4));
        mx0 = fmaxf(mx0, __shfl_xor_sync(0xffffffffu, mx0, 2, 4));
        mx1 = fmaxf(mx1, __shfl_xor_sync(0xffffffffu, mx1, 1, 4));
        mx1 = fmaxf(mx1, __shfl_xor_sync(0xffffffffu, mx1, 2, 4));
        const float mn0 = fmaxf(mrow[0], mx0);
        const float mn1 = fmaxf(mrow[1], mx1);
        float s0 = 0.f, s1 = 0.f;
#pragma unroll
        for (int j = 0; j < 16; j++) {
            sacc[j][0] = __expf(sacc[j][0] - mn0); s0 += sacc[j][0];
            sacc[j][1] = __expf(sacc[j][1] - mn0); s0 += sacc[j][1];
            sacc[j][2] = __expf(sacc[j][2] - mn1); s1 += sacc[j][2];
            sacc[j][3] = __expf(sacc[j][3] - mn1); s1 += sacc[j][3];
        }
        s0 += __shfl_xor_sync(0xffffffffu, s0, 1, 4);
        s0 += __shfl_xor_sync(0xffffffffu, s0, 2, 4);
        s1 += __shfl_xor_sync(0xffffffffu, s1, 1, 4);
        s1 += __shfl_xor_sync(0xffffffffu, s1, 2, 4);
        const float c0 = __expf(mrow[0] - mn0);
        const float c1 = __expf(mrow[1] - mn1);
        lrow_[0] = lrow_[0] * c0 + s0; mrow[0] = mn0;
        lrow_[1] = lrow_[1] * c1 + s1; mrow[1] = mn1;
#pragma unroll
        for (int j = 0; j < 8; j++) {
            oacc[j][0] *= c0; oacc[j][1] *= c0;
            oacc[j][2] *= c1; oacc[j][3] *= c1;
        }

        // ---- O += P V (3-pass split; P from registers) ----
        const uint32_t vbase = 2u * ((lane & 15) * AROW + ((lane >> 4) & 1) * 8);
#pragma unroll
        for (int kk = 0; kk < 8; kk++) {
            uint32_t ah[4], al[4];
            float p00 = sacc[2 * kk][0],     p01 = sacc[2 * kk][1];
            float p02 = sacc[2 * kk][2],     p03 = sacc[2 * kk][3];
            float p10 = sacc[2 * kk + 1][0], p11 = sacc[2 * kk + 1][1];
            float p12 = sacc[2 * kk + 1][2], p13 = sacc[2 * kk + 1][3];
            ah[0] = pk(p00, p01); ah[1] = pk(p02, p03);
            ah[2] = pk(p10, p11); ah[3] = pk(p12, p13);
            al[0] = pk(p00 - bf_hi_f(p00), p01 - bf_hi_f(p01));
            al[1] = pk(p02 - bf_hi_f(p02), p03 - bf_hi_f(p03));
            al[2] = pk(p10 - bf_hi_f(p10), p11 - bf_hi_f(p11));
            al[3] = pk(p12 - bf_hi_f(p12), p13 - bf_hi_f(p13));
            const uint32_t vrow = 2u * (16 * kk * AROW) + vbase;
#pragma unroll
            for (int j2 = 0; j2 < 4; j2++) {
                uint32_t vf[4];
                ldsm_x4t(vf, bVh + vrow + 2u * (16 * j2));
                mma_bf16(oacc[2 * j2],     ah, vf[0], vf[1]);
                mma_bf16(oacc[2 * j2],     al, vf[0], vf[1]);
                mma_bf16(oacc[2 * j2 + 1], ah, vf[2], vf[3]);
                mma_bf16(oacc[2 * j2 + 1], al, vf[2], vf[3]);
            }
#pragma unroll
            for (int j2 = 0; j2 < 4; j2++) {
                uint32_t vf[4];
                ldsm_x4t(vf, bVl + vrow + 2u * (16 * j2));
                mma_bf16(oacc[2 * j2],     ah, vf[0], vf[1]);
                mma_bf16(oacc[2 * j2 + 1], ah, vf[2], vf[3]);
            }
        }
        __syncthreads();
    }

    // epilogue: normalize, write bf16 hi/lo Ob planes
    const float inv0 = 1.f / lrow_[0];
    const float inv1 = 1.f / lrow_[1];
#pragma unroll
    for (int j = 0; j < 8; j++) {
        const int col = head * DK + 8 * j + 2 * (lane & 3);
        float o0 = oacc[j][0] * inv0, o1 = oacc[j][1] * inv0;
        float o2 = oacc[j][2] * inv1, o3 = oacc[j][3] * inv1;
        *(uint32_t*)(g_Obh + (size_t)row0g * HID + col) = pk(bf_hi_f(o0), bf_hi_f(o1));
        *(uint32_t*)(g_Obl + (size_t)row0g * HID + col) = pk(o0 - bf_hi_f(o0), o1 - bf_hi_f(o1));
        *(uint32_t*)(g_Obh + (size_t)row1g * HID + col) = pk(bf_hi_f(o2), bf_hi_f(o3));
        *(uint32_t*)(g_Obl + (size_t)row1g * HID + col) = pk(o2 - bf_hi_f(o2), o3 - bf_hi_f(o3));
    }
}

// ---------------------------------------------------------------------------
extern "C" void kernel_launch(void* const* d_in, const int* in_sizes, int n_in,
                              void* d_out, int out_size) {
    const float* q    = (const float*)d_in[0];
    const float* k    = (const float*)d_in[1];
    const float* v    = (const float*)d_in[2];
    const int*   mask = (const int*)  d_in[3];
    const float* Wq   = (const float*)d_in[4];
    const float* bq   = (const float*)d_in[5];
    const float* Wk   = (const float*)d_in[6];
    const float* bk   = (const float*)d_in[7];
    const float* Wv   = (const float*)d_in[8];
    const float* bv   = (const float*)d_in[9];
    const float* Wo   = (const float*)d_in[10];
    const float* bo   = (const float*)d_in[11];
    float* out = (float*)d_out;

    static bool attr_set = false;
    if (!attr_set) {
        cudaFuncSetAttribute(attn_kernel, cudaFuncAttributeMaxDynamicSharedMemorySize,
                             ASMEM_BYTES);
        cudaFuncSetAttribute(qkv_gemm, cudaFuncAttributeMaxDynamicSharedMemorySize,
                             GEMM_SMEM);
        cudaFuncSetAttribute(out_gemm, cudaFuncAttributeMaxDynamicSharedMemorySize,
                             GEMM_SMEM);
        attr_set = true;
    }

    cvt_inputs<<<dim3(SEQ * HID / 4 / 256, 3), 256>>>(q, k, v);
    cvt_weights<<<dim3(HID * HID / 4 / 256, 4), 256>>>(Wq, Wk, Wv, Wo);
    pack_mask<<<SEQ * (SEQ / 32) / 256, 256>>>(mask);
    qkv_gemm<<<dim3(SEQ / 128, HID / 128, 3), 256, GEMM_SMEM>>>(bq, bk, bv);
    attn_kernel<<<dim3(SEQ / 128, NHEAD), 256, ASMEM_BYTES>>>();
    out_gemm<<<dim3(SEQ / 128, HID / 128), 256, GEMM_SMEM>>>(bo, out);
}

// round 10
// speedup vs baseline: 1.1419x; 1.1419x over previous
#include <cuda_runtime.h>
#include <cuda_bf16.h>
#include <math.h>
#include <stdint.h>

#define SEQ   2048
#define HID   1024
#define NHEAD 16
#define DK    64

// __device__ scratch (allocation-free rule)
__device__ __nv_bfloat16 g_Xh[3 * SEQ * HID];
__device__ __nv_bfloat16 g_Xl[3 * SEQ * HID];
__device__ __nv_bfloat16 g_Wh[4 * HID * HID];
__device__ __nv_bfloat16 g_Wl[4 * HID * HID];
__device__ __nv_bfloat16 g_Qhh[NHEAD * SEQ * DK];
__device__ __nv_bfloat16 g_Qll[NHEAD * SEQ * DK];
__device__ __nv_bfloat16 g_Khh[NHEAD * SEQ * DK];
__device__ __nv_bfloat16 g_Kll[NHEAD * SEQ * DK];
__device__ __nv_bfloat16 g_Vhh[NHEAD * SEQ * DK];
__device__ __nv_bfloat16 g_Vll[NHEAD * SEQ * DK];
__device__ __nv_bfloat16 g_Obh[SEQ * HID];
__device__ __nv_bfloat16 g_Obl[SEQ * HID];
__device__ uint32_t g_mbits[SEQ * (SEQ / 32)];

// ---------------------------------------------------------------------------
// helpers
// ---------------------------------------------------------------------------
__device__ __forceinline__ uint32_t smem_u32(const void* p) {
    uint32_t r;
    asm("{ .reg .u64 t; cvta.to.shared.u64 t, %1; cvt.u32.u64 %0, t; }"
        : "=r"(r) : "l"(p));
    return r;
}
__device__ __forceinline__ void ldsm_x4(uint32_t r[4], uint32_t addr) {
    asm volatile("ldmatrix.sync.aligned.m8n8.x4.shared.b16 {%0,%1,%2,%3}, [%4];"
                 : "=r"(r[0]), "=r"(r[1]), "=r"(r[2]), "=r"(r[3]) : "r"(addr));
}
__device__ __forceinline__ void ldsm_x2(uint32_t r[2], uint32_t addr) {
    asm volatile("ldmatrix.sync.aligned.m8n8.x2.shared.b16 {%0,%1}, [%2];"
                 : "=r"(r[0]), "=r"(r[1]) : "r"(addr));
}
__device__ __forceinline__ void ldsm_x4t(uint32_t r[4], uint32_t addr) {
    asm volatile("ldmatrix.sync.aligned.m8n8.x4.trans.shared.b16 {%0,%1,%2,%3}, [%4];"
                 : "=r"(r[0]), "=r"(r[1]), "=r"(r[2]), "=r"(r[3]) : "r"(addr));
}
__device__ __forceinline__ void mma_bf16(float d[4], const uint32_t a[4],
                                         uint32_t b0, uint32_t b1) {
    asm volatile(
        "mma.sync.aligned.m16n8k16.row.col.f32.bf16.bf16.f32 "
        "{%0,%1,%2,%3}, {%4,%5,%6,%7}, {%8,%9}, {%0,%1,%2,%3};"
        : "+f"(d[0]), "+f"(d[1]), "+f"(d[2]), "+f"(d[3])
        : "r"(a[0]), "r"(a[1]), "r"(a[2]), "r"(a[3]), "r"(b0), "r"(b1));
}
__device__ __forceinline__ uint32_t pk(float x, float y) {
    uint32_t r;
    asm("cvt.rn.bf16x2.f32 %0, %1, %2;" : "=r"(r) : "f"(y), "f"(x));
    return r;
}
__device__ __forceinline__ float bf_hi_f(float x) {
    return __bfloat162float(__float2bfloat16(x));
}
__device__ __forceinline__ void cp16(uint32_t saddr, const void* gaddr) {
    asm volatile("cp.async.cg.shared.global [%0], [%1], 16;"
                 :: "r"(saddr), "l"(gaddr) : "memory");
}
#define CP_COMMIT() asm volatile("cp.async.commit_group;" ::: "memory")
#define CP_WAIT2()  asm volatile("cp.async.wait_group 2;" ::: "memory")

// ---------------------------------------------------------------------------
// hi/lo split conversions
// ---------------------------------------------------------------------------
__global__ __launch_bounds__(256) void cvt_inputs(const float* __restrict__ q,
                                                  const float* __restrict__ k,
                                                  const float* __restrict__ v) {
    const int z = blockIdx.y;
    const float* src = (z == 0) ? q : (z == 1) ? k : v;
    __nv_bfloat16* dh = g_Xh + (size_t)z * SEQ * HID;
    __nv_bfloat16* dl = g_Xl + (size_t)z * SEQ * HID;
    const int idx = blockIdx.x * 256 + threadIdx.x;
    float4 x = ((const float4*)src)[idx];
    uint2 h, l;
    h.x = pk(bf_hi_f(x.x), bf_hi_f(x.y));
    h.y = pk(bf_hi_f(x.z), bf_hi_f(x.w));
    l.x = pk(x.x - bf_hi_f(x.x), x.y - bf_hi_f(x.y));
    l.y = pk(x.z - bf_hi_f(x.z), x.w - bf_hi_f(x.w));
    ((uint2*)dh)[idx] = h;
    ((uint2*)dl)[idx] = l;
}

__global__ __launch_bounds__(256) void cvt_weights(const float* __restrict__ wq,
                                                   const float* __restrict__ wk,
                                                   const float* __restrict__ wv,
                                                   const float* __restrict__ wo) {
    const int z = blockIdx.y;
    const float* src = (z == 0) ? wq : (z == 1) ? wk : (z == 2) ? wv : wo;
    __nv_bfloat16* dh = g_Wh + (size_t)z * HID * HID;
    __nv_bfloat16* dl = g_Wl + (size_t)z * HID * HID;
    const int idx = blockIdx.x * 256 + threadIdx.x;
    float4 x = ((const float4*)src)[idx];
    uint2 h, l;
    h.x = pk(bf_hi_f(x.x), bf_hi_f(x.y));
    h.y = pk(bf_hi_f(x.z), bf_hi_f(x.w));
    l.x = pk(x.x - bf_hi_f(x.x), x.y - bf_hi_f(x.y));
    l.y = pk(x.z - bf_hi_f(x.z), x.w - bf_hi_f(x.w));
    ((uint2*)dh)[idx] = h;
    ((uint2*)dl)[idx] = l;
}

// ---------------------------------------------------------------------------
// mask bit-pack
// ---------------------------------------------------------------------------
__global__ __launch_bounds__(256) void pack_mask(const int* __restrict__ mask) {
    int widx = blockIdx.x * 256 + threadIdx.x;
    int q = widx >> 6;
    int w = widx & 63;
    const int4* p = (const int4*)(mask + (size_t)q * SEQ + w * 32);
    uint32_t bits = 0;
#pragma unroll
    for (int i = 0; i < 8; i++) {
        int4 m = p[i];
        bits |= (m.x != 0 ? 1u : 0u) << (4 * i + 0);
        bits |= (m.y != 0 ? 1u : 0u) << (4 * i + 1);
        bits |= (m.z != 0 ? 1u : 0u) << (4 * i + 2);
        bits |= (m.w != 0 ? 1u : 0u) << (4 * i + 3);
    }
    g_mbits[widx] = bits;
}

// ---------------------------------------------------------------------------
// bf16-split GEMM with 4-stage cp.async pipeline (R8 proven config).
// C = A @ W^T + bias; 3 virtual passes [AhBh],[AlBh],[AhBl] over K=1024.
// CTA 128x128, BK=32, 8 warps (2m x 4n), warp tile 64x32.
// ---------------------------------------------------------------------------
#define SROW 40                       // bf16/row (32 + 8 pad), 80 B pitch
#define TILE_BYTES (128 * SROW * 2)   // 10240
#define STAGE_BYTES (2 * TILE_BYTES)  // A + B = 20480
#define NSTAGE 4
#define GEMM_SMEM (NSTAGE * STAGE_BYTES)   // 81920

template <int MODE>
__device__ __forceinline__ void gemm_body(const __nv_bfloat16* __restrict__ Ah,
                                          const __nv_bfloat16* __restrict__ Al,
                                          const __nv_bfloat16* __restrict__ Bh,
                                          const __nv_bfloat16* __restrict__ Bl,
                                          const float* __restrict__ bias,
                                          float* __restrict__ Cf,
                                          __nv_bfloat16* __restrict__ Chi,
                                          __nv_bfloat16* __restrict__ Clo) {
    extern __shared__ char dynsm[];
    const uint32_t sb = smem_u32(dynsm);

    const int tid  = threadIdx.x;
    const int lane = tid & 31;
    const int w    = tid >> 5;
    const int wm   = w >> 2;
    const int wn   = w & 3;
    const int m0   = blockIdx.x * 128;
    const int n0   = blockIdx.y * 128;

    const int lrow = tid >> 2;          // 0..63
    const int lc16 = tid & 3;           // 16B chunk in row

    float acc[4][4][4];
#pragma unroll
    for (int i = 0; i < 4; i++)
#pragma unroll
        for (int j = 0; j < 4; j++)
#pragma unroll
            for (int e = 0; e < 4; e++) acc[i][j][e] = 0.f;

    auto issue = [&](int t) {
        const int pass = t >> 5;
        const int k0   = (t & 31) * 32;
        const __nv_bfloat16* As = (pass == 1) ? Al : Ah;
        const __nv_bfloat16* Bs = (pass == 2) ? Bl : Bh;
        const uint32_t st = sb + (uint32_t)(t & (NSTAGE - 1)) * STAGE_BYTES;
        const uint32_t so = (uint32_t)(lrow * 80 + lc16 * 16);
        cp16(st + so,                         As + (size_t)(m0 + lrow) * HID + k0 + lc16 * 8);
        cp16(st + so + 64 * 80,               As + (size_t)(m0 + lrow + 64) * HID + k0 + lc16 * 8);
        cp16(st + TILE_BYTES + so,            Bs + (size_t)(n0 + lrow) * HID + k0 + lc16 * 8);
        cp16(st + TILE_BYTES + so + 64 * 80,  Bs + (size_t)(n0 + lrow + 64) * HID + k0 + lc16 * 8);
        CP_COMMIT();
    };

    issue(0); issue(1); issue(2);

    const int NT = 96;
    for (int t = 0; t < NT; t++) {
        CP_WAIT2();
        __syncthreads();
        if (t + 3 < NT) issue(t + 3);

        const uint32_t sAb = sb + (uint32_t)(t & (NSTAGE - 1)) * STAGE_BYTES;
        const uint32_t sBb = sAb + TILE_BYTES;
        uint32_t afr[4][4], bfr[4][2];
#pragma unroll
        for (int kk = 0; kk < 2; kk++) {
#pragma unroll
            for (int i = 0; i < 4; i++)
                ldsm_x4(afr[i], sAb + 2u * ((wm * 64 + 16 * i + (lane & 15)) * SROW
                                            + kk * 16 + ((lane >> 4) & 1) * 8));
#pragma unroll
            for (int j = 0; j < 4; j++)
                ldsm_x2(bfr[j], sBb + 2u * ((wn * 32 + 8 * j + (lane & 7)) * SROW
                                            + kk * 16 + ((lane >> 3) & 1) * 8));
#pragma unroll
            for (int i = 0; i < 4; i++)
#pragma unroll
                for (int j = 0; j < 4; j++)
                    mma_bf16(acc[i][j], afr[i], bfr[j][0], bfr[j][1]);
        }
    }

    // epilogue
#pragma unroll
    for (int j = 0; j < 4; j++) {
        const int gn0 = n0 + wn * 32 + 8 * j + 2 * (lane & 3);
        const float b0 = __ldg(bias + gn0);
        const float b1 = __ldg(bias + gn0 + 1);
#pragma unroll
        for (int i = 0; i < 4; i++) {
            const int r0 = m0 + wm * 64 + 16 * i + (lane >> 2);
            const int r1 = r0 + 8;
            float c0 = acc[i][j][0] + b0, c1 = acc[i][j][1] + b1;
            float c2 = acc[i][j][2] + b0, c3 = acc[i][j][3] + b1;
            if (MODE == 1) {
                *(float2*)(Cf + (size_t)r0 * HID + gn0) = make_float2(c0, c1);
                *(float2*)(Cf + (size_t)r1 * HID + gn0) = make_float2(c2, c3);
            } else {
                const int head = gn0 >> 6;
                const int d    = gn0 & 63;
                size_t i0 = ((size_t)head * SEQ + r0) * DK + d;
                size_t i1 = ((size_t)head * SEQ + r1) * DK + d;
                *(uint32_t*)(Chi + i0) = pk(bf_hi_f(c0), bf_hi_f(c1));
                *(uint32_t*)(Clo + i0) = pk(c0 - bf_hi_f(c0), c1 - bf_hi_f(c1));
                *(uint32_t*)(Chi + i1) = pk(bf_hi_f(c2), bf_hi_f(c3));
                *(uint32_t*)(Clo + i1) = pk(c2 - bf_hi_f(c2), c3 - bf_hi_f(c3));
            }
        }
    }
}

__global__ __launch_bounds__(256, 2) void qkv_gemm(
    const float* __restrict__ bq, const float* __restrict__ bk,
    const float* __restrict__ bv) {
    const int z = blockIdx.z;
    const __nv_bfloat16* Ah = g_Xh + (size_t)z * SEQ * HID;
    const __nv_bfloat16* Al = g_Xl + (size_t)z * SEQ * HID;
    const __nv_bfloat16* Bh = g_Wh + (size_t)z * HID * HID;
    const __nv_bfloat16* Bl = g_Wl + (size_t)z * HID * HID;
    const float* bias = (z == 0) ? bq : (z == 1) ? bk : bv;
    __nv_bfloat16 *Ch, *Cl;
    if (z == 0)      { Ch = g_Qhh; Cl = g_Qll; }
    else if (z == 1) { Ch = g_Khh; Cl = g_Kll; }
    else             { Ch = g_Vhh; Cl = g_Vll; }
    gemm_body<0>(Ah, Al, Bh, Bl, bias, nullptr, Ch, Cl);
}

__global__ __launch_bounds__(256, 2) void out_gemm(
    const float* __restrict__ bo, float* __restrict__ out) {
    gemm_body<1>(g_Obh, g_Obl, g_Wh + (size_t)3 * HID * HID,
                 g_Wl + (size_t)3 * HID * HID, bo, out, nullptr, nullptr);
}

// ---------------------------------------------------------------------------
// Attention: per (128 q-rows, head) CTA. 8 warps x 16 q-rows. Keyblock 128.
// Q fragments in registers (loaded once, direct from global).
// K/V in smem via synchronous uint4 loads (R8-proven). x4/x4t ldmatrix.
// ---------------------------------------------------------------------------
#define AROW 72
#define ATILE (128 * AROW)                // bf16 elems per tile
#define ASMEM_BYTES (4 * ATILE * 2)       // Kh Kl Vh Vl = 73728 B

__global__ __launch_bounds__(256) void attn_kernel() {
    extern __shared__ __nv_bfloat16 sm[];
    __nv_bfloat16* sKh = sm;
    __nv_bfloat16* sKl = sm + ATILE;
    __nv_bfloat16* sVh = sm + 2 * ATILE;
    __nv_bfloat16* sVl = sm + 3 * ATILE;

    const int tid  = threadIdx.x;
    const int lane = tid & 31;
    const int w    = tid >> 5;
    const int head = blockIdx.y;
    const int q0   = blockIdx.x * 128;

    const uint32_t bKh = smem_u32(sKh), bKl = smem_u32(sKl);
    const uint32_t bVh = smem_u32(sVh), bVl = smem_u32(sVl);

    const size_t hbase = (size_t)head * SEQ * DK;
    const int row0g = q0 + 16 * w + (lane >> 2);
    const int row1g = row0g + 8;
    const int cfr   = 2 * (lane & 3);

    // Q fragments in registers (A-layout m16k16 per kk) — R9-proven
    uint32_t qfh[4][4], qfl[4][4];
#pragma unroll
    for (int kk = 0; kk < 4; kk++) {
        const size_t c = kk * 16 + cfr;
        qfh[kk][0] = *(const uint32_t*)(g_Qhh + hbase + (size_t)row0g * DK + c);
        qfh[kk][1] = *(const uint32_t*)(g_Qhh + hbase + (size_t)row1g * DK + c);
        qfh[kk][2] = *(const uint32_t*)(g_Qhh + hbase + (size_t)row0g * DK + c + 8);
        qfh[kk][3] = *(const uint32_t*)(g_Qhh + hbase + (size_t)row1g * DK + c + 8);
        qfl[kk][0] = *(const uint32_t*)(g_Qll + hbase + (size_t)row0g * DK + c);
        qfl[kk][1] = *(const uint32_t*)(g_Qll + hbase + (size_t)row1g * DK + c);
        qfl[kk][2] = *(const uint32_t*)(g_Qll + hbase + (size_t)row0g * DK + c + 8);
        qfl[kk][3] = *(const uint32_t*)(g_Qll + hbase + (size_t)row1g * DK + c + 8);
    }

    float oacc[8][4];
#pragma unroll
    for (int j = 0; j < 8; j++)
#pragma unroll
        for (int e = 0; e < 4; e++) oacc[j][e] = 0.f;
    float mrow[2] = {-1e30f, -1e30f};
    float lsum[2] = {0.f, 0.f};

    for (int kb = 0; kb < SEQ / 128; kb++) {
        __syncthreads();
#pragma unroll
        for (int q = 0; q < 4; q++) {
            int idx = tid + q * 256;
            int r   = idx >> 3;
            int cc  = (idx & 7) * 8;
            size_t g = hbase + (size_t)(kb * 128 + r) * DK + cc;
            *(uint4*)(sKh + r * AROW + cc) = *(const uint4*)(g_Khh + g);
            *(uint4*)(sKl + r * AROW + cc) = *(const uint4*)(g_Kll + g);
            *(uint4*)(sVh + r * AROW + cc) = *(const uint4*)(g_Vhh + g);
            *(uint4*)(sVl + r * AROW + cc) = *(const uint4*)(g_Vll + g);
        }
        __syncthreads();

        // ---- S = Q K^T (3-pass split), K via x4 ldmatrix ----
        float sacc[16][4];
#pragma unroll
        for (int j = 0; j < 16; j++)
#pragma unroll
            for (int e = 0; e < 4; e++) sacc[j][e] = 0.f;

        const uint32_t kroff = 2u * (((lane & 7) + ((lane >> 4) & 1) * 8) * AROW
                                     + ((lane >> 3) & 1) * 8);
#pragma unroll
        for (int kk = 0; kk < 4; kk++) {
#pragma unroll
            for (int j2 = 0; j2 < 8; j2++) {
                uint32_t kf[4];
                ldsm_x4(kf, bKh + kroff + 2u * (16 * j2 * AROW + kk * 16));
                mma_bf16(sacc[2 * j2],     qfh[kk], kf[0], kf[1]);
                mma_bf16(sacc[2 * j2],     qfl[kk], kf[0], kf[1]);
                mma_bf16(sacc[2 * j2 + 1], qfh[kk], kf[2], kf[3]);
                mma_bf16(sacc[2 * j2 + 1], qfl[kk], kf[2], kf[3]);
            }
#pragma unroll
            for (int j2 = 0; j2 < 8; j2++) {
                uint32_t kf[4];
                ldsm_x4(kf, bKl + kroff + 2u * (16 * j2 * AROW + kk * 16));
                mma_bf16(sacc[2 * j2],     qfh[kk], kf[0], kf[1]);
                mma_bf16(sacc[2 * j2 + 1], qfh[kk], kf[2], kf[3]);
            }
        }

        // ---- mask (quirk: masked -> literal 0.0) + scale ----
        uint32_t mw0[4], mw1[4];
#pragma unroll
        for (int i = 0; i < 4; i++) {
            mw0[i] = g_mbits[(size_t)row0g * 64 + kb * 4 + i];
            mw1[i] = g_mbits[(size_t)row1g * 64 + kb * 4 + i];
        }
#pragma unroll
        for (int j = 0; j < 16; j++) {
            int kl = 8 * j + 2 * (lane & 3);
            uint32_t w0 = mw0[kl >> 5], w1 = mw1[kl >> 5];
            int b = kl & 31;
            sacc[j][0] = ((w0 >> b) & 1)       ? sacc[j][0] * 0.125f : 0.f;
            sacc[j][1] = ((w0 >> (b + 1)) & 1) ? sacc[j][1] * 0.125f : 0.f;
            sacc[j][2] = ((w1 >> b) & 1)       ? sacc[j][2] * 0.125f : 0.f;
            sacc[j][3] = ((w1 >> (b + 1)) & 1) ? sacc[j][3] * 0.125f : 0.f;
        }

        // ---- online softmax ----
        float mx0 = -1e30f, mx1 = -1e30f;
#pragma unroll
        for (int j = 0; j < 16; j++) {
            mx0 = fmaxf(mx0, fmaxf(sacc[j][0], sacc[j][1]));
            mx1 = fmaxf(mx1, fmaxf(sacc[j][2], sacc[j][3]));
        }
        mx0 = fmaxf(mx0, __shfl_xor_sync(0xffffffffu, mx0, 1, 4));
        mx0 = fmaxf(mx0, __shfl_xor_sync(0xffffffffu, mx0, 2, 4));
        mx1 = fmaxf(mx1, __shfl_xor_sync(0xffffffffu, mx1, 1, 4));
        mx1 = fmaxf(mx1, __shfl_xor_sync(0xffffffffu, mx1, 2, 4));
        const float mn0 = fmaxf(mrow[0], mx0);
        const float mn1 = fmaxf(mrow[1], mx1);
        float s0 = 0.f, s1 = 0.f;
#pragma unroll
        for (int j = 0; j < 16; j++) {
            sacc[j][0] = __expf(sacc[j][0] - mn0); s0 += sacc[j][0];
            sacc[j][1] = __expf(sacc[j][1] - mn0); s0 += sacc[j][1];
            sacc[j][2] = __expf(sacc[j][2] - mn1); s1 += sacc[j][2];
            sacc[j][3] = __expf(sacc[j][3] - mn1); s1 += sacc[j][3];
        }
        s0 += __shfl_xor_sync(0xffffffffu, s0, 1, 4);
        s0 += __shfl_xor_sync(0xffffffffu, s0, 2, 4);
        s1 += __shfl_xor_sync(0xffffffffu, s1, 1, 4);
        s1 += __shfl_xor_sync(0xffffffffu, s1, 2, 4);
        const float c0 = __expf(mrow[0] - mn0);
        const float c1 = __expf(mrow[1] - mn1);
        lsum[0] = lsum[0] * c0 + s0; mrow[0] = mn0;
        lsum[1] = lsum[1] * c1 + s1; mrow[1] = mn1;
#pragma unroll
        for (int j = 0; j < 8; j++) {
            oacc[j][0] *= c0; oacc[j][1] *= c0;
            oacc[j][2] *= c1; oacc[j][3] *= c1;
        }

        // ---- O += P V (3-pass split; P from registers, V via x4t) ----
        const uint32_t vbase = 2u * ((lane & 15) * AROW + ((lane >> 4) & 1) * 8);
#pragma unroll
        for (int kk = 0; kk < 8; kk++) {
            uint32_t ah[4], al[4];
            float p00 = sacc[2 * kk][0],     p01 = sacc[2 * kk][1];
            float p02 = sacc[2 * kk][2],     p03 = sacc[2 * kk][3];
            float p10 = sacc[2 * kk + 1][0], p11 = sacc[2 * kk + 1][1];
            float p12 = sacc[2 * kk + 1][2], p13 = sacc[2 * kk + 1][3];
            ah[0] = pk(p00, p01); ah[1] = pk(p02, p03);
            ah[2] = pk(p10, p11); ah[3] = pk(p12, p13);
            al[0] = pk(p00 - bf_hi_f(p00), p01 - bf_hi_f(p01));
            al[1] = pk(p02 - bf_hi_f(p02), p03 - bf_hi_f(p03));
            al[2] = pk(p10 - bf_hi_f(p10), p11 - bf_hi_f(p11));
            al[3] = pk(p12 - bf_hi_f(p12), p13 - bf_hi_f(p13));
            const uint32_t vrow = 2u * (16 * kk * AROW) + vbase;
#pragma unroll
            for (int j2 = 0; j2 < 4; j2++) {
                uint32_t vf[4];
                ldsm_x4t(vf, bVh + vrow + 2u * (16 * j2));
                mma_bf16(oacc[2 * j2],     ah, vf[0], vf[1]);
                mma_bf16(oacc[2 * j2],     al, vf[0], vf[1]);
                mma_bf16(oacc[2 * j2 + 1], ah, vf[2], vf[3]);
                mma_bf16(oacc[2 * j2 + 1], al, vf[2], vf[3]);
            }
#pragma unroll
            for (int j2 = 0; j2 < 4; j2++) {
                uint32_t vf[4];
                ldsm_x4t(vf, bVl + vrow + 2u * (16 * j2));
                mma_bf16(oacc[2 * j2],     ah, vf[0], vf[1]);
                mma_bf16(oacc[2 * j2 + 1], ah, vf[2], vf[3]);
            }
        }
    }

    // epilogue: normalize, write bf16 hi/lo Ob planes
    const float inv0 = 1.f / lsum[0];
    const float inv1 = 1.f / lsum[1];
#pragma unroll
    for (int j = 0; j < 8; j++) {
        const int col = head * DK + 8 * j + 2 * (lane & 3);
        float o0 = oacc[j][0] * inv0, o1 = oacc[j][1] * inv0;
        float o2 = oacc[j][2] * inv1, o3 = oacc[j][3] * inv1;
        *(uint32_t*)(g_Obh + (size_t)row0g * HID + col) = pk(bf_hi_f(o0), bf_hi_f(o1));
        *(uint32_t*)(g_Obl + (size_t)row0g * HID + col) = pk(o0 - bf_hi_f(o0), o1 - bf_hi_f(o1));
        *(uint32_t*)(g_Obh + (size_t)row1g * HID + col) = pk(bf_hi_f(o2), bf_hi_f(o3));
        *(uint32_t*)(g_Obl + (size_t)row1g * HID + col) = pk(o2 - bf_hi_f(o2), o3 - bf_hi_f(o3));
    }
}

// ---------------------------------------------------------------------------
extern "C" void kernel_launch(void* const* d_in, const int* in_sizes, int n_in,
                              void* d_out, int out_size) {
    const float* q    = (const float*)d_in[0];
    const float* k    = (const float*)d_in[1];
    const float* v    = (const float*)d_in[2];
    const int*   mask = (const int*)  d_in[3];
    const float* Wq   = (const float*)d_in[4];
    const float* bq   = (const float*)d_in[5];
    const float* Wk   = (const float*)d_in[6];
    const float* bk   = (const float*)d_in[7];
    const float* Wv   = (const float*)d_in[8];
    const float* bv   = (const float*)d_in[9];
    const float* Wo   = (const float*)d_in[10];
    const float* bo   = (const float*)d_in[11];
    float* out = (float*)d_out;

    static bool attr_set = false;
    if (!attr_set) {
        cudaFuncSetAttribute(attn_kernel, cudaFuncAttributeMaxDynamicSharedMemorySize,
                             ASMEM_BYTES);
        cudaFuncSetAttribute(qkv_gemm, cudaFuncAttributeMaxDynamicSharedMemorySize,
                             GEMM_SMEM);
        cudaFuncSetAttribute(out_gemm, cudaFuncAttributeMaxDynamicSharedMemorySize,
                             GEMM_SMEM);
        attr_set = true;
    }

    cvt_inputs<<<dim3(SEQ * HID / 4 / 256, 3), 256>>>(q, k, v);
    cvt_weights<<<dim3(HID * HID / 4 / 256, 4), 256>>>(Wq, Wk, Wv, Wo);
    pack_mask<<<SEQ * (SEQ / 32) / 256, 256>>>(mask);
    qkv_gemm<<<dim3(SEQ / 128, HID / 128, 3), 256, GEMM_SMEM>>>(bq, bk, bv);
    attn_kernel<<<dim3(SEQ / 128, NHEAD), 256, ASMEM_BYTES>>>();
    out_gemm<<<dim3(SEQ / 128, HID / 128), 256, GEMM_SMEM>>>(bo, out);
}

// round 11
// speedup vs baseline: 1.5638x; 1.3695x over previous
#include <cuda_runtime.h>
#include <cuda_fp16.h>
#include <math.h>
#include <stdint.h>

#define SEQ   2048
#define HID   1024
#define NHEAD 16
#define DK    64

// __device__ scratch (allocation-free rule) — fp16 hi/lo planes
__device__ __half g_Xh[3 * SEQ * HID];
__device__ __half g_Xl[3 * SEQ * HID];
__device__ __half g_Wh[4 * HID * HID];          // weights: hi only (B operand)
__device__ __half g_Qhh[NHEAD * SEQ * DK];
__device__ __half g_Qll[NHEAD * SEQ * DK];
__device__ __half g_Khh[NHEAD * SEQ * DK];      // K: hi only used
__device__ __half g_Vhh[NHEAD * SEQ * DK];      // V: hi only used
__device__ __half g_Obh[SEQ * HID];
__device__ __half g_Obl[SEQ * HID];
__device__ uint32_t g_mbits[SEQ * (SEQ / 32)];

// ---------------------------------------------------------------------------
// helpers
// ---------------------------------------------------------------------------
__device__ __forceinline__ uint32_t smem_u32(const void* p) {
    uint32_t r;
    asm("{ .reg .u64 t; cvta.to.shared.u64 t, %1; cvt.u32.u64 %0, t; }"
        : "=r"(r) : "l"(p));
    return r;
}
__device__ __forceinline__ void ldsm_x4(uint32_t r[4], uint32_t addr) {
    asm volatile("ldmatrix.sync.aligned.m8n8.x4.shared.b16 {%0,%1,%2,%3}, [%4];"
                 : "=r"(r[0]), "=r"(r[1]), "=r"(r[2]), "=r"(r[3]) : "r"(addr));
}
__device__ __forceinline__ void ldsm_x2(uint32_t r[2], uint32_t addr) {
    asm volatile("ldmatrix.sync.aligned.m8n8.x2.shared.b16 {%0,%1}, [%2];"
                 : "=r"(r[0]), "=r"(r[1]) : "r"(addr));
}
__device__ __forceinline__ void ldsm_x4t(uint32_t r[4], uint32_t addr) {
    asm volatile("ldmatrix.sync.aligned.m8n8.x4.trans.shared.b16 {%0,%1,%2,%3}, [%4];"
                 : "=r"(r[0]), "=r"(r[1]), "=r"(r[2]), "=r"(r[3]) : "r"(addr));
}
__device__ __forceinline__ void mma_f16(float d[4], const uint32_t a[4],
                                        uint32_t b0, uint32_t b1) {
    asm volatile(
        "mma.sync.aligned.m16n8k16.row.col.f32.f16.f16.f32 "
        "{%0,%1,%2,%3}, {%4,%5,%6,%7}, {%8,%9}, {%0,%1,%2,%3};"
        : "+f"(d[0]), "+f"(d[1]), "+f"(d[2]), "+f"(d[3])
        : "r"(a[0]), "r"(a[1]), "r"(a[2]), "r"(a[3]), "r"(b0), "r"(b1));
}
// pack fp16x2: low half = x, high half = y
__device__ __forceinline__ uint32_t pkh(float x, float y) {
    uint32_t r;
    asm("cvt.rn.f16x2.f32 %0, %1, %2;" : "=r"(r) : "f"(y), "f"(x));
    return r;
}
__device__ __forceinline__ float h_hi_f(float x) {
    return __half2float(__float2half_rn(x));
}
__device__ __forceinline__ void cp16(uint32_t saddr, const void* gaddr) {
    asm volatile("cp.async.cg.shared.global [%0], [%1], 16;"
                 :: "r"(saddr), "l"(gaddr) : "memory");
}
#define CP_COMMIT() asm volatile("cp.async.commit_group;" ::: "memory")
#define CP_WAIT2()  asm volatile("cp.async.wait_group 2;" ::: "memory")

// ---------------------------------------------------------------------------
// fp16 hi/lo split conversions
// ---------------------------------------------------------------------------
__global__ __launch_bounds__(256) void cvt_inputs(const float* __restrict__ q,
                                                  const float* __restrict__ k,
                                                  const float* __restrict__ v) {
    const int z = blockIdx.y;
    const float* src = (z == 0) ? q : (z == 1) ? k : v;
    __half* dh = g_Xh + (size_t)z * SEQ * HID;
    __half* dl = g_Xl + (size_t)z * SEQ * HID;
    const int idx = blockIdx.x * 256 + threadIdx.x;
    float4 x = ((const float4*)src)[idx];
    uint2 h, l;
    h.x = pkh(h_hi_f(x.x), h_hi_f(x.y));
    h.y = pkh(h_hi_f(x.z), h_hi_f(x.w));
    l.x = pkh(x.x - h_hi_f(x.x), x.y - h_hi_f(x.y));
    l.y = pkh(x.z - h_hi_f(x.z), x.w - h_hi_f(x.w));
    ((uint2*)dh)[idx] = h;
    ((uint2*)dl)[idx] = l;
}

__global__ __launch_bounds__(256) void cvt_weights(const float* __restrict__ wq,
                                                   const float* __restrict__ wk,
                                                   const float* __restrict__ wv,
                                                   const float* __restrict__ wo) {
    const int z = blockIdx.y;
    const float* src = (z == 0) ? wq : (z == 1) ? wk : (z == 2) ? wv : wo;
    __half* dh = g_Wh + (size_t)z * HID * HID;
    const int idx = blockIdx.x * 256 + threadIdx.x;
    float4 x = ((const float4*)src)[idx];
    uint2 h;
    h.x = pkh(h_hi_f(x.x), h_hi_f(x.y));
    h.y = pkh(h_hi_f(x.z), h_hi_f(x.w));
    ((uint2*)dh)[idx] = h;
}

// ---------------------------------------------------------------------------
// mask bit-pack
// ---------------------------------------------------------------------------
__global__ __launch_bounds__(256) void pack_mask(const int* __restrict__ mask) {
    int widx = blockIdx.x * 256 + threadIdx.x;
    int q = widx >> 6;
    int w = widx & 63;
    const int4* p = (const int4*)(mask + (size_t)q * SEQ + w * 32);
    uint32_t bits = 0;
#pragma unroll
    for (int i = 0; i < 8; i++) {
        int4 m = p[i];
        bits |= (m.x != 0 ? 1u : 0u) << (4 * i + 0);
        bits |= (m.y != 0 ? 1u : 0u) << (4 * i + 1);
        bits |= (m.z != 0 ? 1u : 0u) << (4 * i + 2);
        bits |= (m.w != 0 ? 1u : 0u) << (4 * i + 3);
    }
    g_mbits[widx] = bits;
}

// ---------------------------------------------------------------------------
// fp16 2-pass GEMM with 4-stage cp.async pipeline (R8-proven structure).
// C = A @ W^T + bias; passes [AhBh],[AlBh] over K=1024 -> NT = 64 tiles.
// CTA 128x128, BK=32, 8 warps (2m x 4n), warp tile 64x32.
// ---------------------------------------------------------------------------
#define SROW 40                       // fp16/row (32 + 8 pad), 80 B pitch
#define TILE_BYTES (128 * SROW * 2)   // 10240
#define STAGE_BYTES (2 * TILE_BYTES)  // A + B = 20480
#define NSTAGE 4
#define GEMM_SMEM (NSTAGE * STAGE_BYTES)   // 81920

template <int MODE>
__device__ __forceinline__ void gemm_body(const __half* __restrict__ Ah,
                                          const __half* __restrict__ Al,
                                          const __half* __restrict__ Bh,
                                          const float* __restrict__ bias,
                                          float* __restrict__ Cf,
                                          __half* __restrict__ Chi,
                                          __half* __restrict__ Clo) {
    extern __shared__ char dynsm[];
    const uint32_t sb = smem_u32(dynsm);

    const int tid  = threadIdx.x;
    const int lane = tid & 31;
    const int w    = tid >> 5;
    const int wm   = w >> 2;
    const int wn   = w & 3;
    const int m0   = blockIdx.x * 128;
    const int n0   = blockIdx.y * 128;

    const int lrow = tid >> 2;
    const int lc16 = tid & 3;

    float acc[4][4][4];
#pragma unroll
    for (int i = 0; i < 4; i++)
#pragma unroll
        for (int j = 0; j < 4; j++)
#pragma unroll
            for (int e = 0; e < 4; e++) acc[i][j][e] = 0.f;

    auto issue = [&](int t) {
        const int pass = t >> 5;
        const int k0   = (t & 31) * 32;
        const __half* As = pass ? Al : Ah;
        const uint32_t st = sb + (uint32_t)(t & (NSTAGE - 1)) * STAGE_BYTES;
        const uint32_t so = (uint32_t)(lrow * 80 + lc16 * 16);
        cp16(st + so,                         As + (size_t)(m0 + lrow) * HID + k0 + lc16 * 8);
        cp16(st + so + 64 * 80,               As + (size_t)(m0 + lrow + 64) * HID + k0 + lc16 * 8);
        cp16(st + TILE_BYTES + so,            Bh + (size_t)(n0 + lrow) * HID + k0 + lc16 * 8);
        cp16(st + TILE_BYTES + so + 64 * 80,  Bh + (size_t)(n0 + lrow + 64) * HID + k0 + lc16 * 8);
        CP_COMMIT();
    };

    issue(0); issue(1); issue(2);

    const int NT = 64;    // 2 passes x 32 K-tiles
    for (int t = 0; t < NT; t++) {
        CP_WAIT2();
        __syncthreads();
        if (t + 3 < NT) issue(t + 3);

        const uint32_t sAb = sb + (uint32_t)(t & (NSTAGE - 1)) * STAGE_BYTES;
        const uint32_t sBb = sAb + TILE_BYTES;
        uint32_t afr[4][4], bfr[4][2];
#pragma unroll
        for (int kk = 0; kk < 2; kk++) {
#pragma unroll
            for (int i = 0; i < 4; i++)
                ldsm_x4(afr[i], sAb + 2u * ((wm * 64 + 16 * i + (lane & 15)) * SROW
                                            + kk * 16 + ((lane >> 4) & 1) * 8));
#pragma unroll
            for (int j = 0; j < 4; j++)
                ldsm_x2(bfr[j], sBb + 2u * ((wn * 32 + 8 * j + (lane & 7)) * SROW
                                            + kk * 16 + ((lane >> 3) & 1) * 8));
#pragma unroll
            for (int i = 0; i < 4; i++)
#pragma unroll
                for (int j = 0; j < 4; j++)
                    mma_f16(acc[i][j], afr[i], bfr[j][0], bfr[j][1]);
        }
    }

    // epilogue
#pragma unroll
    for (int j = 0; j < 4; j++) {
        const int gn0 = n0 + wn * 32 + 8 * j + 2 * (lane & 3);
        const float b0 = __ldg(bias + gn0);
        const float b1 = __ldg(bias + gn0 + 1);
#pragma unroll
        for (int i = 0; i < 4; i++) {
            const int r0 = m0 + wm * 64 + 16 * i + (lane >> 2);
            const int r1 = r0 + 8;
            float c0 = acc[i][j][0] + b0, c1 = acc[i][j][1] + b1;
            float c2 = acc[i][j][2] + b0, c3 = acc[i][j][3] + b1;
            if (MODE == 1) {
                *(float2*)(Cf + (size_t)r0 * HID + gn0) = make_float2(c0, c1);
                *(float2*)(Cf + (size_t)r1 * HID + gn0) = make_float2(c2, c3);
            } else {
                const int head = gn0 >> 6;
                const int d    = gn0 & 63;
                size_t i0 = ((size_t)head * SEQ + r0) * DK + d;
                size_t i1 = ((size_t)head * SEQ + r1) * DK + d;
                *(uint32_t*)(Chi + i0) = pkh(h_hi_f(c0), h_hi_f(c1));
                *(uint32_t*)(Chi + i1) = pkh(h_hi_f(c2), h_hi_f(c3));
                if (Clo) {
                    *(uint32_t*)(Clo + i0) = pkh(c0 - h_hi_f(c0), c1 - h_hi_f(c1));
                    *(uint32_t*)(Clo + i1) = pkh(c2 - h_hi_f(c2), c3 - h_hi_f(c3));
                }
            }
        }
    }
}

__global__ __launch_bounds__(256, 2) void qkv_gemm(
    const float* __restrict__ bq, const float* __restrict__ bk,
    const float* __restrict__ bv) {
    const int z = blockIdx.z;
    const __half* Ah = g_Xh + (size_t)z * SEQ * HID;
    const __half* Al = g_Xl + (size_t)z * SEQ * HID;
    const __half* Bh = g_Wh + (size_t)z * HID * HID;
    const float* bias = (z == 0) ? bq : (z == 1) ? bk : bv;
    __half *Ch, *Cl;
    if (z == 0)      { Ch = g_Qhh; Cl = g_Qll; }   // Q: hi+lo (A operand of S)
    else if (z == 1) { Ch = g_Khh; Cl = nullptr; } // K: hi only (B operand)
    else             { Ch = g_Vhh; Cl = nullptr; } // V: hi only (B operand)
    gemm_body<0>(Ah, Al, Bh, bias, nullptr, Ch, Cl);
}

__global__ __launch_bounds__(256, 2) void out_gemm(
    const float* __restrict__ bo, float* __restrict__ out) {
    gemm_body<1>(g_Obh, g_Obl, g_Wh + (size_t)3 * HID * HID, bo, out,
                 nullptr, nullptr);
}

// ---------------------------------------------------------------------------
// Attention: per (128 q-rows, head) CTA. 8 warps x 16 q-rows. Keyblock 128.
// fp16 2-pass: S = (Qh+Ql)·Kh ; O += (Ph+Pl)·Vh.  K/V hi-only in smem.
// ---------------------------------------------------------------------------
#define AROW 72
#define ATILE (128 * AROW)                // fp16 elems per tile
#define ASMEM_BYTES (2 * ATILE * 2)       // Kh, Vh = 36864 B

__global__ __launch_bounds__(256) void attn_kernel() {
    extern __shared__ __half sm[];
    __half* sKh = sm;
    __half* sVh = sm + ATILE;

    const int tid  = threadIdx.x;
    const int lane = tid & 31;
    const int w    = tid >> 5;
    const int head = blockIdx.y;
    const int q0   = blockIdx.x * 128;

    const uint32_t bKh = smem_u32(sKh);
    const uint32_t bVh = smem_u32(sVh);

    const size_t hbase = (size_t)head * SEQ * DK;
    const int row0g = q0 + 16 * w + (lane >> 2);
    const int row1g = row0g + 8;
    const int cfr   = 2 * (lane & 3);

    // Q fragments in registers (A-layout m16k16 per kk)
    uint32_t qfh[4][4], qfl[4][4];
#pragma unroll
    for (int kk = 0; kk < 4; kk++) {
        const size_t c = kk * 16 + cfr;
        qfh[kk][0] = *(const uint32_t*)(g_Qhh + hbase + (size_t)row0g * DK + c);
        qfh[kk][1] = *(const uint32_t*)(g_Qhh + hbase + (size_t)row1g * DK + c);
        qfh[kk][2] = *(const uint32_t*)(g_Qhh + hbase + (size_t)row0g * DK + c + 8);
        qfh[kk][3] = *(const uint32_t*)(g_Qhh + hbase + (size_t)row1g * DK + c + 8);
        qfl[kk][0] = *(const uint32_t*)(g_Qll + hbase + (size_t)row0g * DK + c);
        qfl[kk][1] = *(const uint32_t*)(g_Qll + hbase + (size_t)row1g * DK + c);
        qfl[kk][2] = *(const uint32_t*)(g_Qll + hbase + (size_t)row0g * DK + c + 8);
        qfl[kk][3] = *(const uint32_t*)(g_Qll + hbase + (size_t)row1g * DK + c + 8);
    }

    float oacc[8][4];
#pragma unroll
    for (int j = 0; j < 8; j++)
#pragma unroll
        for (int e = 0; e < 4; e++) oacc[j][e] = 0.f;
    float mrow[2] = {-1e30f, -1e30f};
    float lsum[2] = {0.f, 0.f};

    for (int kb = 0; kb < SEQ / 128; kb++) {
        __syncthreads();
        // K/V hi tiles: 128 rows x 64 cols fp16 each -> 1024 uint4 per tile
#pragma unroll
        for (int q = 0; q < 4; q++) {
            int idx = tid + q * 256;
            int r   = idx >> 3;
            int cc  = (idx & 7) * 8;
            size_t g = hbase + (size_t)(kb * 128 + r) * DK + cc;
            *(uint4*)(sKh + r * AROW + cc) = *(const uint4*)(g_Khh + g);
            *(uint4*)(sVh + r * AROW + cc) = *(const uint4*)(g_Vhh + g);
        }
        __syncthreads();

        // ---- S = (Qh + Ql) . Kh^T  (2-pass) ----
        float sacc[16][4];
#pragma unroll
        for (int j = 0; j < 16; j++)
#pragma unroll
            for (int e = 0; e < 4; e++) sacc[j][e] = 0.f;

        const uint32_t kroff = 2u * (((lane & 7) + ((lane >> 4) & 1) * 8) * AROW
                                     + ((lane >> 3) & 1) * 8);
#pragma unroll
        for (int kk = 0; kk < 4; kk++) {
#pragma unroll
            for (int j2 = 0; j2 < 8; j2++) {
                uint32_t kf[4];
                ldsm_x4(kf, bKh + kroff + 2u * (16 * j2 * AROW + kk * 16));
                mma_f16(sacc[2 * j2],     qfh[kk], kf[0], kf[1]);
                mma_f16(sacc[2 * j2],     qfl[kk], kf[0], kf[1]);
                mma_f16(sacc[2 * j2 + 1], qfh[kk], kf[2], kf[3]);
                mma_f16(sacc[2 * j2 + 1], qfl[kk], kf[2], kf[3]);
            }
        }

        // ---- mask (quirk: masked -> literal 0.0) + scale ----
        uint32_t mw0[4], mw1[4];
#pragma unroll
        for (int i = 0; i < 4; i++) {
            mw0[i] = g_mbits[(size_t)row0g * 64 + kb * 4 + i];
            mw1[i] = g_mbits[(size_t)row1g * 64 + kb * 4 + i];
        }
#pragma unroll
        for (int j = 0; j < 16; j++) {
            int kl = 8 * j + 2 * (lane & 3);
            uint32_t w0 = mw0[kl >> 5], w1 = mw1[kl >> 5];
            int b = kl & 31;
            sacc[j][0] = ((w0 >> b) & 1)       ? sacc[j][0] * 0.125f : 0.f;
            sacc[j][1] = ((w0 >> (b + 1)) & 1) ? sacc[j][1] * 0.125f : 0.f;
            sacc[j][2] = ((w1 >> b) & 1)       ? sacc[j][2] * 0.125f : 0.f;
            sacc[j][3] = ((w1 >> (b + 1)) & 1) ? sacc[j][3] * 0.125f : 0.f;
        }

        // ---- online softmax ----
        float mx0 = -1e30f, mx1 = -1e30f;
#pragma unroll
        for (int j = 0; j < 16; j++) {
            mx0 = fmaxf(mx0, fmaxf(sacc[j][0], sacc[j][1]));
            mx1 = fmaxf(mx1, fmaxf(sacc[j][2], sacc[j][3]));
        }
        mx0 = fmaxf(mx0, __shfl_xor_sync(0xffffffffu, mx0, 1, 4));
        mx0 = fmaxf(mx0, __shfl_xor_sync(0xffffffffu, mx0, 2, 4));
        mx1 = fmaxf(mx1, __shfl_xor_sync(0xffffffffu, mx1, 1, 4));
        mx1 = fmaxf(mx1, __shfl_xor_sync(0xffffffffu, mx1, 2, 4));
        const float mn0 = fmaxf(mrow[0], mx0);
        const float mn1 = fmaxf(mrow[1], mx1);
        float s0 = 0.f, s1 = 0.f;
#pragma unroll
        for (int j = 0; j < 16; j++) {
            sacc[j][0] = __expf(sacc[j][0] - mn0); s0 += sacc[j][0];
            sacc[j][1] = __expf(sacc[j][1] - mn0); s0 += sacc[j][1];
            sacc[j][2] = __expf(sacc[j][2] - mn1); s1 += sacc[j][2];
            sacc[j][3] = __expf(sacc[j][3] - mn1); s1 += sacc[j][3];
        }
        s0 += __shfl_xor_sync(0xffffffffu, s0, 1, 4);
        s0 += __shfl_xor_sync(0xffffffffu, s0, 2, 4);
        s1 += __shfl_xor_sync(0xffffffffu, s1, 1, 4);
        s1 += __shfl_xor_sync(0xffffffffu, s1, 2, 4);
        const float c0 = __expf(mrow[0] - mn0);
        const float c1 = __expf(mrow[1] - mn1);
        lsum[0] = lsum[0] * c0 + s0; mrow[0] = mn0;
        lsum[1] = lsum[1] * c1 + s1; mrow[1] = mn1;
#pragma unroll
        for (int j = 0; j < 8; j++) {
            oacc[j][0] *= c0; oacc[j][1] *= c0;
            oacc[j][2] *= c1; oacc[j][3] *= c1;
        }

        // ---- O += (Ph + Pl) . Vh  (2-pass; P from registers) ----
        const uint32_t vbase = 2u * ((lane & 15) * AROW + ((lane >> 4) & 1) * 8);
#pragma unroll
        for (int kk = 0; kk < 8; kk++) {
            uint32_t ah[4], al[4];
            float p00 = sacc[2 * kk][0],     p01 = sacc[2 * kk][1];
            float p02 = sacc[2 * kk][2],     p03 = sacc[2 * kk][3];
            float p10 = sacc[2 * kk + 1][0], p11 = sacc[2 * kk + 1][1];
            float p12 = sacc[2 * kk + 1][2], p13 = sacc[2 * kk + 1][3];
            ah[0] = pkh(p00, p01); ah[1] = pkh(p02, p03);
            ah[2] = pkh(p10, p11); ah[3] = pkh(p12, p13);
            al[0] = pkh(p00 - h_hi_f(p00), p01 - h_hi_f(p01));
            al[1] = pkh(p02 - h_hi_f(p02), p03 - h_hi_f(p03));
            al[2] = pkh(p10 - h_hi_f(p10), p11 - h_hi_f(p11));
            al[3] = pkh(p12 - h_hi_f(p12), p13 - h_hi_f(p13));
            const uint32_t vrow = 2u * (16 * kk * AROW) + vbase;
#pragma unroll
            for (int j2 = 0; j2 < 4; j2++) {
                uint32_t vf[4];
                ldsm_x4t(vf, bVh + vrow + 2u * (16 * j2));
                mma_f16(oacc[2 * j2],     ah, vf[0], vf[1]);
                mma_f16(oacc[2 * j2],     al, vf[0], vf[1]);
                mma_f16(oacc[2 * j2 + 1], ah, vf[2], vf[3]);
                mma_f16(oacc[2 * j2 + 1], al, vf[2], vf[3]);
            }
        }
    }

    // epilogue: normalize, write fp16 hi/lo Ob planes
    const float inv0 = 1.f / lsum[0];
    const float inv1 = 1.f / lsum[1];
#pragma unroll
    for (int j = 0; j < 8; j++) {
        const int col = head * DK + 8 * j + 2 * (lane & 3);
        float o0 = oacc[j][0] * inv0, o1 = oacc[j][1] * inv0;
        float o2 = oacc[j][2] * inv1, o3 = oacc[j][3] * inv1;
        *(uint32_t*)(g_Obh + (size_t)row0g * HID + col) = pkh(h_hi_f(o0), h_hi_f(o1));
        *(uint32_t*)(g_Obl + (size_t)row0g * HID + col) = pkh(o0 - h_hi_f(o0), o1 - h_hi_f(o1));
        *(uint32_t*)(g_Obh + (size_t)row1g * HID + col) = pkh(h_hi_f(o2), h_hi_f(o3));
        *(uint32_t*)(g_Obl + (size_t)row1g * HID + col) = pkh(o2 - h_hi_f(o2), o3 - h_hi_f(o3));
    }
}

// ---------------------------------------------------------------------------
extern "C" void kernel_launch(void* const* d_in, const int* in_sizes, int n_in,
                              void* d_out, int out_size) {
    const float* q    = (const float*)d_in[0];
    const float* k    = (const float*)d_in[1];
    const float* v    = (const float*)d_in[2];
    const int*   mask = (const int*)  d_in[3];
    const float* Wq   = (const float*)d_in[4];
    const float* bq   = (const float*)d_in[5];
    const float* Wk   = (const float*)d_in[6];
    const float* bk   = (const float*)d_in[7];
    const float* Wv   = (const float*)d_in[8];
    const float* bv   = (const float*)d_in[9];
    const float* Wo   = (const float*)d_in[10];
    const float* bo   = (const float*)d_in[11];
    float* out = (float*)d_out;

    static bool attr_set = false;
    if (!attr_set) {
        cudaFuncSetAttribute(attn_kernel, cudaFuncAttributeMaxDynamicSharedMemorySize,
                             ASMEM_BYTES);
        cudaFuncSetAttribute(qkv_gemm, cudaFuncAttributeMaxDynamicSharedMemorySize,
                             GEMM_SMEM);
        cudaFuncSetAttribute(out_gemm, cudaFuncAttributeMaxDynamicSharedMemorySize,
                             GEMM_SMEM);
        attr_set = true;
    }

    cvt_inputs<<<dim3(SEQ * HID / 4 / 256, 3), 256>>>(q, k, v);
    cvt_weights<<<dim3(HID * HID / 4 / 256, 4), 256>>>(Wq, Wk, Wv, Wo);
    pack_mask<<<SEQ * (SEQ / 32) / 256, 256>>>(mask);
    qkv_gemm<<<dim3(SEQ / 128, HID / 128, 3), 256, GEMM_SMEM>>>(bq, bk, bv);
    attn_kernel<<<dim3(SEQ / 128, NHEAD), 256, ASMEM_BYTES>>>();
    out_gemm<<<dim3(SEQ / 128, HID / 128), 256, GEMM_SMEM>>>(bo, out);
}